// round 8
// baseline (speedup 1.0000x reference)
#include <cuda_runtime.h>
#include <cstdint>

#define NN   50000
#define BB   2
#define FIN  128
#define FOUT 64
#define OC   128          // B*FOUT = gather row width
#define EE   800000
#define ROWS (BB * NN)    // 100000

// Scratch (allocation-free rule: __device__ globals)
__device__ float g_xt[NN * OC];   // x@W laid out as (n, b*FOUT + o)  -- gather source
__device__ int   g_cnt[NN];       // per-row edge count
__device__ int   g_off[NN];       // CSR row offsets (exclusive)
__device__ int   g_fill[NN];      // fill cursors for permutation
__device__ int   g_col[EE];       // CSR-ordered source columns
__device__ float g_val[EE];       // CSR-ordered edge values

// ---------------------------------------------------------------------------
// Fused GEMM (round-6 version — best measured: 139us).
// Warp processes 8 rows; lane owns column pairs (2l,2l+1) and (64+2l,64+2l+1).
// ---------------------------------------------------------------------------
__global__ __launch_bounds__(128) void gemm_kernel(
    const float* __restrict__ x, const float* __restrict__ W,
    const float* __restrict__ Wself, const float* __restrict__ bself,
    float* __restrict__ out)
{
    extern __shared__ float ws[];   // ws[f*128 + c]: c<64 -> W[f][c], c>=64 -> Wself[f][c-64]
    int t = threadIdx.x;
    for (int idx = t; idx < FIN * 128; idx += 128) {
        int f = idx >> 7, c = idx & 127;
        ws[idx] = (c < 64) ? W[(f << 6) + c] : Wself[(f << 6) + (c - 64)];
    }
    __syncthreads();

    int lane = t & 31;
    long warp = (long)blockIdx.x * 4 + (t >> 5);
    long r0 = warp << 3;
    const float* xp = x + r0 * FIN;

    unsigned long long acc0[8], acc1[8];
    #pragma unroll
    for (int i = 0; i < 8; i++) { acc0[i] = 0ull; acc1[i] = 0ull; }

    const int c0 = lane * 2;
    const float* wsp = ws + c0;

    for (int fc = 0; fc < FIN; fc += 4) {
        float4 xv[8];
        #pragma unroll
        for (int i = 0; i < 8; i++)
            xv[i] = *(const float4*)(xp + i * FIN + fc);

        #pragma unroll
        for (int j = 0; j < 4; j++) {
            unsigned long long w0 = *(const unsigned long long*)(wsp + (fc + j) * 128);
            unsigned long long w1 = *(const unsigned long long*)(wsp + (fc + j) * 128 + 64);
            #pragma unroll
            for (int i = 0; i < 8; i++) {
                float xf = (j == 0) ? xv[i].x : (j == 1) ? xv[i].y : (j == 2) ? xv[i].z : xv[i].w;
                unsigned long long xx;
                asm("mov.b64 %0, {%1, %1};" : "=l"(xx) : "f"(xf));
                asm("fma.rn.f32x2 %0, %1, %2, %0;" : "+l"(acc0[i]) : "l"(xx), "l"(w0));
                asm("fma.rn.f32x2 %0, %1, %2, %0;" : "+l"(acc1[i]) : "l"(xx), "l"(w1));
            }
        }
    }

    int b  = (int)(r0 / NN);
    int n0 = (int)(r0 % NN);
    float2 bb = *(const float2*)(bself + c0);
    #pragma unroll
    for (int i = 0; i < 8; i++) {
        int n = n0 + i;
        float2 v0, v1;
        asm("mov.b64 {%0, %1}, %2;" : "=f"(v0.x), "=f"(v0.y) : "l"(acc0[i]));
        asm("mov.b64 {%0, %1}, %2;" : "=f"(v1.x), "=f"(v1.y) : "l"(acc1[i]));
        *(float2*)(g_xt + (long)n * OC + b * FOUT + c0) = v0;          // gather source
        v1.x += bb.x; v1.y += bb.y;                                     // self path + bias
        *(float2*)(out + ((long)b * NN + n) * FOUT + c0) = v1;
    }
}

// ---------------------------------------------------------------------------
// CSR build step 1: histogram of destination rows.
// ---------------------------------------------------------------------------
__global__ __launch_bounds__(256) void hist_kernel(const int* __restrict__ erow)
{
    int e = blockIdx.x * 256 + threadIdx.x;          // EE/256 = 3125 blocks, exact
    atomicAdd(&g_cnt[erow[e]], 1);
}

// ---------------------------------------------------------------------------
// CSR build step 2: single-block exclusive scan over 50000 counts.
// Thread owns a 49-element segment; block-level Hillis-Steele over seg sums.
// ---------------------------------------------------------------------------
#define SCAN_T 1024
#define SEG 49      // 1024*49 = 50176 >= NN
__global__ __launch_bounds__(SCAN_T) void scan_kernel()
{
    __shared__ int ssum[SCAN_T];
    int t = threadIdx.x;
    int base = t * SEG;
    int s = 0;
    for (int i = 0; i < SEG; i++) {
        int idx = base + i;
        if (idx < NN) s += g_cnt[idx];
    }
    ssum[t] = s;
    __syncthreads();
    for (int d = 1; d < SCAN_T; d <<= 1) {
        int v = (t >= d) ? ssum[t - d] : 0;
        __syncthreads();
        ssum[t] += v;
        __syncthreads();
    }
    int run = (t > 0) ? ssum[t - 1] : 0;
    for (int i = 0; i < SEG; i++) {
        int idx = base + i;
        if (idx >= NN) break;
        g_off[idx]  = run;
        g_fill[idx] = run;
        run += g_cnt[idx];
    }
}

// ---------------------------------------------------------------------------
// CSR build step 3: permute (col, val) into CSR order.
// ---------------------------------------------------------------------------
__global__ __launch_bounds__(256) void fill_kernel(
    const int* __restrict__ erow, const int* __restrict__ ecol,
    const float* __restrict__ eval)
{
    int e = blockIdx.x * 256 + threadIdx.x;
    int pos = atomicAdd(&g_fill[erow[e]], 1);
    g_col[pos] = ecol[e];
    g_val[pos] = eval[e];
}

// ---------------------------------------------------------------------------
// Pull-mode gather + fused epilogue. Warp per destination row n.
// Lane l accumulates floats [4l,4l+4) of the 128-wide row over all edges,
// then out[b][n][o] = relu(self + agg): lanes 0..15 -> b=0, 16..31 -> b=1.
// No atomics, no g_agg, no memset.
// ---------------------------------------------------------------------------
__global__ __launch_bounds__(256) void gather_kernel(float* __restrict__ out)
{
    int n = blockIdx.x * 8 + (threadIdx.x >> 5);     // NN/8 = 6250 blocks, exact
    int lane = threadIdx.x & 31;
    int beg = g_off[n];
    int m   = g_cnt[n];

    float4 acc = make_float4(0.f, 0.f, 0.f, 0.f);
    const float* __restrict__ xt = g_xt;

    int j = 0;
    for (; j + 4 <= m; j += 4) {                     // 4 gathers in flight (MLP)
        int   c0 = g_col[beg + j],     c1 = g_col[beg + j + 1];
        int   c2 = g_col[beg + j + 2], c3 = g_col[beg + j + 3];
        float v0 = g_val[beg + j],     v1 = g_val[beg + j + 1];
        float v2 = g_val[beg + j + 2], v3 = g_val[beg + j + 3];
        float4 s0 = *(const float4*)(xt + (long)c0 * OC + lane * 4);
        float4 s1 = *(const float4*)(xt + (long)c1 * OC + lane * 4);
        float4 s2 = *(const float4*)(xt + (long)c2 * OC + lane * 4);
        float4 s3 = *(const float4*)(xt + (long)c3 * OC + lane * 4);
        acc.x += v0 * s0.x; acc.y += v0 * s0.y; acc.z += v0 * s0.z; acc.w += v0 * s0.w;
        acc.x += v1 * s1.x; acc.y += v1 * s1.y; acc.z += v1 * s1.z; acc.w += v1 * s1.w;
        acc.x += v2 * s2.x; acc.y += v2 * s2.y; acc.z += v2 * s2.z; acc.w += v2 * s2.w;
        acc.x += v3 * s3.x; acc.y += v3 * s3.y; acc.z += v3 * s3.z; acc.w += v3 * s3.w;
    }
    for (; j < m; j++) {
        int   c = g_col[beg + j];
        float v = g_val[beg + j];
        float4 s = *(const float4*)(xt + (long)c * OC + lane * 4);
        acc.x += v * s.x; acc.y += v * s.y; acc.z += v * s.z; acc.w += v * s.w;
    }

    int b = lane >> 4;                               // cols 0..63 -> b=0, 64..127 -> b=1
    float* op = out + ((long)b * NN + n) * FOUT + (lane & 15) * 4;
    float4 sc = *(float4*)op;
    sc.x = fmaxf(sc.x + acc.x, 0.f);
    sc.y = fmaxf(sc.y + acc.y, 0.f);
    sc.z = fmaxf(sc.z + acc.z, 0.f);
    sc.w = fmaxf(sc.w + acc.w, 0.f);
    *(float4*)op = sc;
}

extern "C" void kernel_launch(void* const* d_in, const int* in_sizes, int n_in,
                              void* d_out, int out_size)
{
    const float* x     = (const float*)d_in[0];
    const float* W     = (const float*)d_in[1];
    const float* Wself = (const float*)d_in[2];
    const float* bself = (const float*)d_in[3];
    const int*   erow  = (const int*)d_in[4];
    const int*   ecol  = (const int*)d_in[5];
    const float* eval  = (const float*)d_in[6];
    float* out = (float*)d_out;

    void* cntp = nullptr;
    cudaGetSymbolAddress(&cntp, g_cnt);
    cudaMemsetAsync(cntp, 0, (size_t)NN * sizeof(int), 0);

    cudaFuncSetAttribute(gemm_kernel, cudaFuncAttributeMaxDynamicSharedMemorySize, 65536);
    gemm_kernel<<<ROWS / 32, 128, 65536>>>(x, W, Wself, bself, out);   // 3125 blocks

    hist_kernel<<<EE / 256, 256>>>(erow);                              // 3125 blocks
    scan_kernel<<<1, SCAN_T>>>();
    fill_kernel<<<EE / 256, 256>>>(erow, ecol, eval);                  // 3125 blocks
    gather_kernel<<<NN / 8, 256>>>(out);                               // 6250 blocks
}